// round 3
// baseline (speedup 1.0000x reference)
#include <cuda_runtime.h>
#include <math.h>

#define DT 0.01f
#define SEG   32                      // actions per thread
#define TPB   256
#define NBLK  1024                    // 8388608 / (32*256)
#define TILE  (TPB * SEG)             // 8192 floats / block
#define SSTR  36                      // padded smem stride per segment

// Persistent device state. g_ticket is NEVER reset: generation = ticket/NBLK,
// and flags encode gen*4 + state (1=aggregate ready, 2=inclusive prefix ready).
// Flag values are monotone, so stale values from prior replays are ignored.
__device__ int            g_ticket;
__device__ volatile int   g_flag[NBLK];
__device__ volatile float g_agg [NBLK][4];
__device__ volatile float g_pref[NBLK][4];

// Tuple (A,P,X,V): v' = A*v + V ; x' = x + P*v + X.  comp(f,g) = apply f then g.
__device__ __forceinline__ float4 comp(float4 f, float4 g) {
    float4 r;
    r.x = g.x * f.x;
    r.y = f.y + g.y * f.x;
    r.z = f.z + g.y * f.w + g.z;
    r.w = g.x * f.w + g.w;
    return r;
}
__device__ __forceinline__ float4 ident() { return make_float4(1.f, 0.f, 0.f, 0.f); }

__global__ void __launch_bounds__(TPB)
k_scan(const float* __restrict__ act,
       const float* __restrict__ initst,
       const float* __restrict__ mass,
       const float* __restrict__ fric,
       float2* __restrict__ out2)
{
    __shared__ __align__(16) float s[TPB * SSTR];   // input tile; later aliased as output staging
    __shared__ float4 sh[TPB];
    __shared__ int    s_tkt;
    __shared__ float4 s_excl;

    int tid = threadIdx.x;
    if (tid == 0) s_tkt = atomicAdd(&g_ticket, 1);
    __syncthreads();
    int tkt = s_tkt;
    int bid = tkt & (NBLK - 1);
    int gen = tkt >> 10;                            // tkt / NBLK
    int fbase = gen * 4;

    // ---- coalesced tile load -> padded smem (seg-major) ----
    const float4* g4 = reinterpret_cast<const float4*>(act) + (size_t)bid * (TILE / 4);
    #pragma unroll
    for (int r = 0; r < TILE / 4 / TPB; r++) {
        int i4 = tid + TPB * r;
        float4 v = g4[i4];
        *reinterpret_cast<float4*>(&s[(i4 >> 3) * SSTR + (i4 & 7) * 4]) = v;
    }
    __syncthreads();

    float m_safe = fabsf(mass[0]) + 0.001f;
    float beta  = DT / m_safe;
    float alpha = 1.0f - fric[0] * beta;

    // ---- per-thread segment tuple (zero initial state) ----
    const float* my = s + tid * SSTR;
    float v = 0.f, x = 0.f;
    #pragma unroll
    for (int j = 0; j < SEG / 4; j++) {
        float4 a = *reinterpret_cast<const float4*>(my + 4 * j);
        v = alpha * v + beta * a.x; x += DT * v;
        v = alpha * v + beta * a.y; x += DT * v;
        v = alpha * v + beta * a.z; x += DT * v;
        v = alpha * v + beta * a.w; x += DT * v;
    }
    float A = alpha;
    #pragma unroll
    for (int j = 0; j < 5; j++) A *= A;             // alpha^32
    float denom = 1.0f - alpha;
    float P = (denom != 0.f) ? (DT * alpha * (1.f - A) / denom) : (DT * (float)SEG);

    // ---- block scan (Hillis-Steele, non-commutative) ----
    float4 val = make_float4(A, P, x, v);
    sh[tid] = val;
    __syncthreads();
    for (int d = 1; d < TPB; d <<= 1) {
        float4 left;
        if (tid >= d) left = sh[tid - d];
        __syncthreads();
        if (tid >= d) { val = comp(left, val); sh[tid] = val; }
        __syncthreads();
    }
    float4 excl_thr = (tid == 0) ? ident() : sh[tid - 1];

    // ---- decoupled lookback (warp 0) ----
    if (tid < 32) {
        float4 total = sh[TPB - 1];
        if (tid == 0) {
            g_agg[bid][0] = total.x; g_agg[bid][1] = total.y;
            g_agg[bid][2] = total.z; g_agg[bid][3] = total.w;
            __threadfence();
            g_flag[bid] = fbase + 1;
        }
        float4 run = ident();
        int base = bid;
        while (base > 0) {
            int p = base - 1 - tid;                 // lane 0 = nearest predecessor
            int st;
            if (p < 0) st = 2;
            else {
                int f;
                do { f = g_flag[p]; } while (f < fbase + 1);
                st = f - fbase;                     // 1 or 2
            }
            unsigned b2 = __ballot_sync(0xffffffffu, st >= 2);
            int l2 = (b2 == 0) ? 32 : (__ffs(b2) - 1);
            float4 c = ident();
            if (tid <= l2 && p >= 0) {
                __threadfence();
                if (tid == l2)
                    c = make_float4(g_pref[p][0], g_pref[p][1], g_pref[p][2], g_pref[p][3]);
                else
                    c = make_float4(g_agg[p][0], g_agg[p][1], g_agg[p][2], g_agg[p][3]);
            }
            // left-fold: higher lane (earlier block) applied first
            #pragma unroll
            for (int d = 1; d < 32; d <<= 1) {
                float4 up;
                up.x = __shfl_down_sync(0xffffffffu, c.x, d);
                up.y = __shfl_down_sync(0xffffffffu, c.y, d);
                up.z = __shfl_down_sync(0xffffffffu, c.z, d);
                up.w = __shfl_down_sync(0xffffffffu, c.w, d);
                if (tid + d < 32) c = comp(up, c);
            }
            float4 win;
            win.x = __shfl_sync(0xffffffffu, c.x, 0);
            win.y = __shfl_sync(0xffffffffu, c.y, 0);
            win.z = __shfl_sync(0xffffffffu, c.z, 0);
            win.w = __shfl_sync(0xffffffffu, c.w, 0);
            run = comp(win, run);
            if (l2 < 32) break;
            base -= 32;
        }
        if (tid == 0) {
            float4 incl = comp(run, total);
            g_pref[bid][0] = incl.x; g_pref[bid][1] = incl.y;
            g_pref[bid][2] = incl.z; g_pref[bid][3] = incl.w;
            __threadfence();
            g_flag[bid] = fbase + 2;
            s_excl = run;
        }
    }
    __syncthreads();

    // ---- apply prefix to initial state, replay segment ----
    float x0 = initst[0];
    float v0 = initst[1];
    float4 e = comp(s_excl, excl_thr);
    float vv = e.x * v0 + e.w;
    float xx = x0 + e.y * v0 + e.z;

    int g = bid * TPB + tid;
    if (g == 0) out2[0] = make_float2(x0, v0);

    float2 r[SEG];
    #pragma unroll
    for (int j = 0; j < SEG / 4; j++) {
        float4 a = *reinterpret_cast<const float4*>(my + 4 * j);
        vv = alpha * vv + beta * a.x; xx += DT * vv; r[4 * j + 0] = make_float2(xx, vv);
        vv = alpha * vv + beta * a.y; xx += DT * vv; r[4 * j + 1] = make_float2(xx, vv);
        vv = alpha * vv + beta * a.z; xx += DT * vv; r[4 * j + 2] = make_float2(xx, vv);
        vv = alpha * vv + beta * a.w; xx += DT * vv; r[4 * j + 3] = make_float2(xx, vv);
    }

    // ---- staged coalesced output (staging aliases the input tile smem) ----
    float2* sout = reinterpret_cast<float2*>(s);    // 128*(SEG+1)*8 = 33792B <= tile 36864B
    float2* out_base = out2 + 1 + (size_t)bid * TILE;
    #pragma unroll
    for (int half = 0; half < 2; half++) {
        __syncthreads();
        if ((tid >> 7) == half) {
            int t = tid & 127;
            #pragma unroll
            for (int k = 0; k < SEG; k++) sout[t * (SEG + 1) + k] = r[k];
        }
        __syncthreads();
        float2* gdst = out_base + half * (TILE / 2);
        #pragma unroll
        for (int w = 0; w < (TILE / 2) / TPB; w++) {
            int i2 = tid + TPB * w;
            gdst[i2] = sout[(i2 >> 5) * (SEG + 1) + (i2 & 31)];
        }
    }
}

extern "C" void kernel_launch(void* const* d_in, const int* in_sizes, int n_in,
                              void* d_out, int out_size) {
    const float* init = (const float*)d_in[0];
    const float* act  = (const float*)d_in[1];
    const float* mass = (const float*)d_in[2];
    const float* fric = (const float*)d_in[3];
    float2* out2 = (float2*)d_out;

    k_scan<<<NBLK, TPB>>>(act, init, mass, fric, out2);
}

// round 4
// speedup vs baseline: 1.4202x; 1.4202x over previous
#include <cuda_runtime.h>
#include <math.h>

#define DT 0.01f
#define SEG    32                      // actions per thread
#define TPB    256
#define NTILE  1024                    // 8388608 / (32*256)
#define TILE   (TPB * SEG)             // 8192 floats per tile
#define SSTR   36                      // padded smem stride (floats) per segment
#define GRID1  512                     // pass1 blocks (2 tiles each) -> single balanced wave

// Per-tile (block-granularity) affine tuples. (A,P,X,V): v' = A*v + V ; x' = x + P*v + X
__device__ float4 g_blk[NTILE];

__device__ __forceinline__ float4 comp(float4 f, float4 g) {
    float4 r;
    r.x = g.x * f.x;
    r.y = f.y + g.y * f.x;
    r.z = f.z + g.y * f.w + g.z;
    r.w = g.x * f.w + g.w;
    return r;
}
__device__ __forceinline__ float4 ident() { return make_float4(1.f, 0.f, 0.f, 0.f); }

__device__ __forceinline__ float4 shfl_up4(float4 v, int d, unsigned m) {
    float4 r;
    r.x = __shfl_up_sync(m, v.x, d);
    r.y = __shfl_up_sync(m, v.y, d);
    r.z = __shfl_up_sync(m, v.z, d);
    r.w = __shfl_up_sync(m, v.w, d);
    return r;
}
__device__ __forceinline__ float4 shfl_dn4(float4 v, int d, unsigned m) {
    float4 r;
    r.x = __shfl_down_sync(m, v.x, d);
    r.y = __shfl_down_sync(m, v.y, d);
    r.z = __shfl_down_sync(m, v.z, d);
    r.w = __shfl_down_sync(m, v.w, d);
    return r;
}

__device__ __forceinline__ void get_coeffs(const float* mass, const float* fric,
                                           float& alpha, float& beta) {
    float m_safe = fabsf(mass[0]) + 0.001f;
    beta  = DT / m_safe;
    alpha = 1.0f - fric[0] * beta;
}

__device__ __forceinline__ void homo_coeffs(float alpha, float& A, float& P) {
    A = alpha;
    #pragma unroll
    for (int j = 0; j < 5; j++) A *= A;               // alpha^32
    float denom = 1.0f - alpha;
    P = (denom != 0.f) ? (DT * alpha * (1.f - A) / denom) : (DT * (float)SEG);
}

__device__ __forceinline__ void load_tile(const float* __restrict__ act, float* s,
                                          int tid, int tile) {
    const float4* g4 = reinterpret_cast<const float4*>(act) + (size_t)tile * (TILE / 4);
    #pragma unroll
    for (int r = 0; r < TILE / 4 / TPB; r++) {
        int i4 = tid + TPB * r;
        float4 v = g4[i4];
        *reinterpret_cast<float4*>(&s[(i4 >> 3) * SSTR + (i4 & 7) * 4]) = v;
    }
}

// ---------------- Pass 1: per-tile tuple via ordered block reduce ----------------
__global__ void __launch_bounds__(TPB)
k_partial(const float* __restrict__ act,
          const float* __restrict__ mass,
          const float* __restrict__ fric) {
    __shared__ __align__(16) float s[TPB * SSTR];
    __shared__ float4 wtot[TPB / 32];
    int tid = threadIdx.x, lane = tid & 31, wid = tid >> 5;

    float alpha, beta, A, Pc;
    get_coeffs(mass, fric, alpha, beta);
    homo_coeffs(alpha, A, Pc);

    #pragma unroll
    for (int t = 0; t < NTILE / GRID1; t++) {
        int tile = blockIdx.x + t * GRID1;
        load_tile(act, s, tid, tile);
        __syncthreads();

        const float* my = s + tid * SSTR;
        float v = 0.f, x = 0.f;
        #pragma unroll
        for (int j = 0; j < SEG / 4; j++) {
            float4 a = *reinterpret_cast<const float4*>(my + 4 * j);
            v = alpha * v + beta * a.x; x += DT * v;
            v = alpha * v + beta * a.y; x += DT * v;
            v = alpha * v + beta * a.z; x += DT * v;
            v = alpha * v + beta * a.w; x += DT * v;
        }
        float4 val = make_float4(A, Pc, x, v);

        // ordered fold toward lane 0 (lane0 earliest in sequence)
        #pragma unroll
        for (int d = 1; d < 32; d <<= 1) {
            float4 up = shfl_dn4(val, d, 0xffffffffu);
            if (lane + d < 32) val = comp(val, up);
        }
        if (lane == 0) wtot[wid] = val;
        __syncthreads();
        if (tid < TPB / 32) {
            float4 c = wtot[tid];
            #pragma unroll
            for (int d = 1; d < TPB / 32; d <<= 1) {
                float4 up = shfl_dn4(c, d, 0xffu);
                if (tid + d < TPB / 32) c = comp(c, up);
            }
            if (tid == 0) g_blk[tile] = c;
        }
        __syncthreads();     // before smem reuse
    }
}

// ---------------- Pass 2: exclusive scan of 1024 tile tuples ----------------
__global__ void __launch_bounds__(1024)
k_blockscan() {
    __shared__ float4 wt[32];
    int tid = threadIdx.x, lane = tid & 31, wid = tid >> 5;

    float4 val = g_blk[tid];
    #pragma unroll
    for (int d = 1; d < 32; d <<= 1) {
        float4 up = shfl_up4(val, d, 0xffffffffu);
        if (lane >= d) val = comp(up, val);
    }
    if (lane == 31) wt[wid] = val;
    __syncthreads();
    if (wid == 0) {
        float4 c = wt[lane];
        #pragma unroll
        for (int d = 1; d < 32; d <<= 1) {
            float4 up = shfl_up4(c, d, 0xffffffffu);
            if (lane >= d) c = comp(up, c);
        }
        wt[lane] = c;
    }
    __syncthreads();
    float4 wexcl = (wid == 0) ? ident() : wt[wid - 1];
    float4 lexcl = shfl_up4(val, 1, 0xffffffffu);
    if (lane == 0) lexcl = ident();
    g_blk[tid] = comp(wexcl, lexcl);     // exclusive prefix per tile
}

// ---------------- Pass 3: zero-replay + in-block scan + affine fixup + store ----------------
__global__ void __launch_bounds__(TPB)
k_final(const float* __restrict__ act,
        const float* __restrict__ initst,
        const float* __restrict__ mass,
        const float* __restrict__ fric,
        float2* __restrict__ out2) {
    __shared__ __align__(16) float s[TPB * SSTR];         // tile; aliased as output staging
    __shared__ float4 wtot[TPB / 32];
    int tid = threadIdx.x, lane = tid & 31, wid = tid >> 5;
    int bid = blockIdx.x;
    int g   = bid * TPB + tid;

    load_tile(act, s, tid, bid);
    __syncthreads();

    float alpha, beta, A, Pc;
    get_coeffs(mass, fric, alpha, beta);
    homo_coeffs(alpha, A, Pc);

    // zero-state replay, kept in registers
    float2 r[SEG];
    const float* my = s + tid * SSTR;
    float v = 0.f, x = 0.f;
    #pragma unroll
    for (int j = 0; j < SEG / 4; j++) {
        float4 a = *reinterpret_cast<const float4*>(my + 4 * j);
        v = alpha * v + beta * a.x; x += DT * v; r[4 * j + 0] = make_float2(x, v);
        v = alpha * v + beta * a.y; x += DT * v; r[4 * j + 1] = make_float2(x, v);
        v = alpha * v + beta * a.z; x += DT * v; r[4 * j + 2] = make_float2(x, v);
        v = alpha * v + beta * a.w; x += DT * v; r[4 * j + 3] = make_float2(x, v);
    }

    // in-block ordered scan of thread tuples (shuffle-based)
    float4 val = make_float4(A, Pc, x, v);
    #pragma unroll
    for (int d = 1; d < 32; d <<= 1) {
        float4 up = shfl_up4(val, d, 0xffffffffu);
        if (lane >= d) val = comp(up, val);
    }
    if (lane == 31) wtot[wid] = val;
    __syncthreads();
    if (tid < TPB / 32) {
        float4 c = wtot[tid];
        #pragma unroll
        for (int d = 1; d < TPB / 32; d <<= 1) {
            float4 up = shfl_up4(c, d, 0xffu);
            if (tid >= d) c = comp(up, c);
        }
        wtot[tid] = c;
    }
    __syncthreads();
    float4 wexcl = (wid == 0) ? ident() : wtot[wid - 1];
    float4 lexcl = shfl_up4(val, 1, 0xffffffffu);
    if (lane == 0) lexcl = ident();
    float4 e = comp(g_blk[bid], comp(wexcl, lexcl));

    float x0 = initst[0];
    float v0 = initst[1];
    float vin = e.x * v0 + e.w;
    float xin = x0 + e.y * v0 + e.z;

    if (g == 0) out2[0] = make_float2(x0, v0);

    // affine fixup of the zero-state trajectory
    float ap = 1.f, pp = 0.f;
    #pragma unroll
    for (int k = 0; k < SEG; k++) {
        ap *= alpha;
        pp += DT * ap;
        r[k].x = xin + pp * vin + r[k].x;
        r[k].y = ap * vin + r[k].y;
    }

    // staged coalesced output (staging aliases the input tile smem)
    float2* sout = reinterpret_cast<float2*>(s);      // 128*(SEG+1)*8 = 33792B <= 36864B
    float2* out_base = out2 + 1 + (size_t)bid * TILE;
    #pragma unroll
    for (int half = 0; half < 2; half++) {
        __syncthreads();
        if ((tid >> 7) == half) {
            int t = tid & 127;
            #pragma unroll
            for (int k = 0; k < SEG; k++) sout[t * (SEG + 1) + k] = r[k];
        }
        __syncthreads();
        float2* gdst = out_base + half * (TILE / 2);
        #pragma unroll
        for (int w = 0; w < (TILE / 2) / TPB; w++) {
            int i2 = tid + TPB * w;
            gdst[i2] = sout[(i2 >> 5) * (SEG + 1) + (i2 & 31)];
        }
    }
}

extern "C" void kernel_launch(void* const* d_in, const int* in_sizes, int n_in,
                              void* d_out, int out_size) {
    const float* init = (const float*)d_in[0];
    const float* act  = (const float*)d_in[1];
    const float* mass = (const float*)d_in[2];
    const float* fric = (const float*)d_in[3];
    float2* out2 = (float2*)d_out;

    k_partial<<<GRID1, TPB>>>(act, mass, fric);
    k_blockscan<<<1, 1024>>>();
    k_final<<<NTILE, TPB>>>(act, init, mass, fric, out2);
}

// round 5
// speedup vs baseline: 1.5441x; 1.0872x over previous
#include <cuda_runtime.h>
#include <math.h>

#define DT 0.01f
#define SEG    32                      // actions per thread (k_final)
#define TPB    256
#define NTILE  1024                    // 8388608 / 8192
#define TILE   (TPB * SEG)             // 8192 floats per tile
#define SSTR   36                      // padded smem stride (floats) per segment

// Per-tile affine tuples. (A,P,X,V): v' = A*v + V ; x' = x + P*v + X
__device__ float4 g_blk[NTILE];

__device__ __forceinline__ float4 comp(float4 f, float4 g) {
    float4 r;
    r.x = g.x * f.x;
    r.y = f.y + g.y * f.x;
    r.z = f.z + g.y * f.w + g.z;
    r.w = g.x * f.w + g.w;
    return r;
}
__device__ __forceinline__ float4 ident() { return make_float4(1.f, 0.f, 0.f, 0.f); }

__device__ __forceinline__ float4 shfl_up4(float4 v, int d, unsigned m) {
    float4 r;
    r.x = __shfl_up_sync(m, v.x, d);
    r.y = __shfl_up_sync(m, v.y, d);
    r.z = __shfl_up_sync(m, v.z, d);
    r.w = __shfl_up_sync(m, v.w, d);
    return r;
}

__device__ __forceinline__ void get_coeffs(const float* mass, const float* fric,
                                           float& alpha, float& beta) {
    float m_safe = fabsf(mass[0]) + 0.001f;
    beta  = DT / m_safe;
    alpha = 1.0f - fric[0] * beta;
}

// ---------------- Pass 1: per-tile tuple via two parallel reductions ----------------
// v_zero = beta * W,  W = sum_i alpha^(8191-i) * a_i
// x_zero = DT*(beta*S - alpha*beta*W) / (1-alpha),  S = sum_i a_i
__global__ void __launch_bounds__(TPB)
k_partial(const float* __restrict__ act,
          const float* __restrict__ mass,
          const float* __restrict__ fric) {
    __shared__ float2 wred[TPB / 32];
    int tid = threadIdx.x, lane = tid & 31, wid = tid >> 5;

    float alpha, beta;
    get_coeffs(mass, fric, alpha, beta);
    float l2a  = log2f(alpha);
    float w    = exp2f(l2a * (float)(8191 - 4 * tid));  // weight of this thread's first element
    float step = exp2f(l2a * -1024.0f);                 // advance 256 float4s = 1024 elements

    const float4* g4 = reinterpret_cast<const float4*>(act) + (size_t)blockIdx.x * (TILE / 4);

    float acc0 = 0.f, acc1 = 0.f, acc2 = 0.f, acc3 = 0.f;
    float s0 = 0.f, s1 = 0.f, s2 = 0.f, s3 = 0.f;
    #pragma unroll
    for (int r = 0; r < TILE / 4 / TPB; r++) {          // 8 fully independent iterations
        float4 a = g4[r * TPB + tid];
        acc0 = fmaf(a.x, w, acc0);
        acc1 = fmaf(a.y, w, acc1);
        acc2 = fmaf(a.z, w, acc2);
        acc3 = fmaf(a.w, w, acc3);
        s0 += a.x; s1 += a.y; s2 += a.z; s3 += a.w;
        w *= step;
    }
    float ai  = 1.0f / alpha;          // lane offsets within float4: alpha^{-1,-2,-3}
    float ai2 = ai * ai;
    float W = fmaf(ai2 * ai, acc3, fmaf(ai2, acc2, fmaf(ai, acc1, acc0)));
    float S = (s0 + s1) + (s2 + s3);

    #pragma unroll
    for (int d = 16; d > 0; d >>= 1) {
        W += __shfl_down_sync(0xffffffffu, W, d);
        S += __shfl_down_sync(0xffffffffu, S, d);
    }
    if (lane == 0) wred[wid] = make_float2(S, W);
    __syncthreads();
    if (tid == 0) {
        float St = 0.f, Wt = 0.f;
        #pragma unroll
        for (int i = 0; i < TPB / 32; i++) { St += wred[i].x; Wt += wred[i].y; }

        float A = alpha;
        #pragma unroll
        for (int j = 0; j < 13; j++) A *= A;            // alpha^8192
        float denom = 1.0f - alpha;
        if (fabsf(denom) < 1e-12f) denom = 1e-12f;      // guard (not hit for real inputs)
        float P  = DT * alpha * (1.0f - A) / denom;
        float vz = beta * Wt;
        float xz = DT * (beta * St - alpha * vz) / denom;
        g_blk[blockIdx.x] = make_float4(A, P, xz, vz);
    }
}

// ---------------- Pass 2: exclusive scan of 1024 tile tuples ----------------
__global__ void __launch_bounds__(1024)
k_blockscan() {
    __shared__ float4 wt[32];
    int tid = threadIdx.x, lane = tid & 31, wid = tid >> 5;

    float4 val = g_blk[tid];
    #pragma unroll
    for (int d = 1; d < 32; d <<= 1) {
        float4 up = shfl_up4(val, d, 0xffffffffu);
        if (lane >= d) val = comp(up, val);
    }
    if (lane == 31) wt[wid] = val;
    __syncthreads();
    if (wid == 0) {
        float4 c = wt[lane];
        #pragma unroll
        for (int d = 1; d < 32; d <<= 1) {
            float4 up = shfl_up4(c, d, 0xffffffffu);
            if (lane >= d) c = comp(up, c);
        }
        wt[lane] = c;
    }
    __syncthreads();
    float4 wexcl = (wid == 0) ? ident() : wt[wid - 1];
    float4 lexcl = shfl_up4(val, 1, 0xffffffffu);
    if (lane == 0) lexcl = ident();
    g_blk[tid] = comp(wexcl, lexcl);
}

// ---------------- Pass 3: replay + in-block scan + affine fixup + coalesced store ----------------
__global__ void __launch_bounds__(TPB)
k_final(const float* __restrict__ act,
        const float* __restrict__ initst,
        const float* __restrict__ mass,
        const float* __restrict__ fric,
        float2* __restrict__ out2) {
    __shared__ __align__(16) float s[TPB * SSTR];
    __shared__ float4 wtot[TPB / 32];
    int tid = threadIdx.x, lane = tid & 31, wid = tid >> 5;
    int bid = blockIdx.x;
    int g   = bid * TPB + tid;

    // coalesced tile load -> padded smem
    {
        const float4* g4 = reinterpret_cast<const float4*>(act) + (size_t)bid * (TILE / 4);
        #pragma unroll
        for (int r = 0; r < TILE / 4 / TPB; r++) {
            int i4 = tid + TPB * r;
            float4 v = g4[i4];
            *reinterpret_cast<float4*>(&s[(i4 >> 3) * SSTR + (i4 & 7) * 4]) = v;
        }
    }
    __syncthreads();

    float alpha, beta;
    get_coeffs(mass, fric, alpha, beta);
    float A = alpha;
    #pragma unroll
    for (int j = 0; j < 5; j++) A *= A;                 // alpha^32
    float denom = 1.0f - alpha;
    float Pc = (denom != 0.f) ? (DT * alpha * (1.f - A) / denom) : (DT * (float)SEG);

    // zero-state replay, kept in registers
    float2 r[SEG];
    const float* my = s + tid * SSTR;
    float v = 0.f, x = 0.f;
    #pragma unroll
    for (int j = 0; j < SEG / 4; j++) {
        float4 a = *reinterpret_cast<const float4*>(my + 4 * j);
        v = alpha * v + beta * a.x; x += DT * v; r[4 * j + 0] = make_float2(x, v);
        v = alpha * v + beta * a.y; x += DT * v; r[4 * j + 1] = make_float2(x, v);
        v = alpha * v + beta * a.z; x += DT * v; r[4 * j + 2] = make_float2(x, v);
        v = alpha * v + beta * a.w; x += DT * v; r[4 * j + 3] = make_float2(x, v);
    }

    // in-block ordered scan of thread tuples
    float4 val = make_float4(A, Pc, x, v);
    #pragma unroll
    for (int d = 1; d < 32; d <<= 1) {
        float4 up = shfl_up4(val, d, 0xffffffffu);
        if (lane >= d) val = comp(up, val);
    }
    if (lane == 31) wtot[wid] = val;
    __syncthreads();
    if (tid < TPB / 32) {
        float4 c = wtot[tid];
        #pragma unroll
        for (int d = 1; d < TPB / 32; d <<= 1) {
            float4 up = shfl_up4(c, d, 0xffu);
            if (tid >= d) c = comp(up, c);
        }
        wtot[tid] = c;
    }
    __syncthreads();
    float4 wexcl = (wid == 0) ? ident() : wtot[wid - 1];
    float4 lexcl = shfl_up4(val, 1, 0xffffffffu);
    if (lane == 0) lexcl = ident();
    float4 e = comp(g_blk[bid], comp(wexcl, lexcl));

    float x0 = initst[0];
    float v0 = initst[1];
    float vin = e.x * v0 + e.w;
    float xin = x0 + e.y * v0 + e.z;

    if (g == 0) out2[0] = make_float2(x0, v0);

    // affine fixup of the zero-state trajectory
    float ap = 1.f, pp = 0.f;
    #pragma unroll
    for (int k = 0; k < SEG; k++) {
        ap *= alpha;
        pp += DT * ap;
        r[k].x = xin + pp * vin + r[k].x;
        r[k].y = ap * vin + r[k].y;
    }

    // staged coalesced output (staging aliases the input tile smem)
    float2* sout = reinterpret_cast<float2*>(s);
    float2* out_base = out2 + 1 + (size_t)bid * TILE;
    #pragma unroll
    for (int half = 0; half < 2; half++) {
        __syncthreads();
        if ((tid >> 7) == half) {
            int t = tid & 127;
            #pragma unroll
            for (int k = 0; k < SEG; k++) sout[t * (SEG + 1) + k] = r[k];
        }
        __syncthreads();
        float2* gdst = out_base + half * (TILE / 2);
        #pragma unroll
        for (int w = 0; w < (TILE / 2) / TPB; w++) {
            int i2 = tid + TPB * w;
            gdst[i2] = sout[(i2 >> 5) * (SEG + 1) + (i2 & 31)];
        }
    }
}

extern "C" void kernel_launch(void* const* d_in, const int* in_sizes, int n_in,
                              void* d_out, int out_size) {
    const float* init = (const float*)d_in[0];
    const float* act  = (const float*)d_in[1];
    const float* mass = (const float*)d_in[2];
    const float* fric = (const float*)d_in[3];
    float2* out2 = (float2*)d_out;

    k_partial<<<NTILE, TPB>>>(act, mass, fric);
    k_blockscan<<<1, 1024>>>();
    k_final<<<NTILE, TPB>>>(act, init, mass, fric, out2);
}